// round 6
// baseline (speedup 1.0000x reference)
#include <cuda_runtime.h>
#include <math.h>

#define NPART 4096
#define NC 16

#define R_ON2  (1.7f * 1.7f)       /* 2.89  */
#define R_C2   (4.0f)              /* 2.0^2 */
#define CUT_INV_DENOM (1.0f / ((R_C2 - R_ON2) * (R_C2 - R_ON2) * (R_C2 - R_ON2)))
#define ALPHA_F 2.8f

#define NCELL_DIM 16
#define NCELLS (NCELL_DIM * NCELL_DIM * NCELL_DIM)   /* 4096 */
#define INV_CELLW 0.4f                               /* 1 / 2.5 */

#define EBLOCKS 512                                  /* energy kernel blocks */

// scratch (no allocations; __device__ globals are zero-initialized at load,
// and every counter is returned to zero by the end of each launch, so graph
// replays see identical initial state)
__device__ float  g_w[NPART * NC];    // w_i[d] = 0.5*sum_c ct[c]*(E[c,d]+E[d,c])
__device__ float  g_mask[NPART];      // column mask: sum(ct_j) > 0
__device__ float4 g_pos4[NPART];      // x,y,z,radius
__device__ int    g_cellid[NPART];
__device__ int    g_cnt[NCELLS];      // histogram; scatter drains it back to 0
__device__ int    g_start[NCELLS + 1];
__device__ int    g_sortedidx[NPART]; // particle ids grouped by cell
__device__ float  g_part[EBLOCKS];
__device__ unsigned int g_count;      // last-block counter; reset by last block

// ---------------------------------------------------------------------------
// Kernel 1: per-particle contraction w_i = ct_i^T E_sym_i, mask, pos4 pack,
// cell binning. One thread per (particle, dim).
// ---------------------------------------------------------------------------
__global__ __launch_bounds__(128)
void prep_kernel(const float* __restrict__ pos,
                 const float* __restrict__ ct,
                 const float* __restrict__ E,
                 const float* __restrict__ rad) {
    const int t = blockIdx.x * 128 + threadIdx.x;   // 0 .. 65535
    const int i = t >> 4;     // particle
    const int d = t & 15;     // output dim

    // celltype in registers
    const float4* __restrict__ ct4 = (const float4*)(ct + i * NC);
    float4 c0 = ct4[0], c1 = ct4[1], c2 = ct4[2], c3 = ct4[3];
    float sct[16] = {c0.x, c0.y, c0.z, c0.w, c1.x, c1.y, c1.z, c1.w,
                     c2.x, c2.y, c2.z, c2.w, c3.x, c3.y, c3.z, c3.w};

    // row d of E in registers
    const float4* __restrict__ Er4 = (const float4*)(E + i * 256 + d * NC);
    float4 r0 = Er4[0], r1 = Er4[1], r2 = Er4[2], r3 = Er4[3];
    float er[16] = {r0.x, r0.y, r0.z, r0.w, r1.x, r1.y, r1.z, r1.w,
                    r2.x, r2.y, r2.z, r2.w, r3.x, r3.y, r3.z, r3.w};

    // column d of E: 16 scalar loads, 64B-contiguous across lanes, L1-hot
    const float* __restrict__ Ec = E + i * 256 + d;
    float w = 0.0f;
#pragma unroll
    for (int c = 0; c < 16; c++) {
        w = fmaf(sct[c], er[c] + __ldg(Ec + c * 16), w);
    }
    g_w[t] = 0.5f * w;

    if (d == 0) {
        float s = 0.0f;
#pragma unroll
        for (int c = 0; c < 16; c++) s += sct[c];
        g_mask[i] = (s > 0.0f) ? 1.0f : 0.0f;
        float px = pos[3 * i], py = pos[3 * i + 1], pz = pos[3 * i + 2];
        g_pos4[i] = make_float4(px, py, pz, rad[i]);
        int cx = min((int)(px * INV_CELLW), NCELL_DIM - 1);
        int cy = min((int)(py * INV_CELLW), NCELL_DIM - 1);
        int cz = min((int)(pz * INV_CELLW), NCELL_DIM - 1);
        int cell = (cz << 8) | (cy << 4) | cx;
        g_cellid[i] = cell;
        atomicAdd(&g_cnt[cell], 1);
    }
}

// ---------------------------------------------------------------------------
// Kernel 2: exclusive scan of 4096 cell counts. One block, 1024 threads,
// 4 cells per thread (Hillis-Steele on the 1024 partials).
// ---------------------------------------------------------------------------
__global__ __launch_bounds__(1024)
void scan_kernel() {
    __shared__ int s[1024];
    const int tid = threadIdx.x;
    int a = g_cnt[4 * tid + 0];
    int b = g_cnt[4 * tid + 1];
    int c = g_cnt[4 * tid + 2];
    int d = g_cnt[4 * tid + 3];
    int t1 = a, t2 = a + b, t3 = a + b + c, sum = a + b + c + d;
    s[tid] = sum;
    __syncthreads();
    for (int off = 1; off < 1024; off <<= 1) {
        int x = (tid >= off) ? s[tid - off] : 0;
        __syncthreads();
        s[tid] += x;
        __syncthreads();
    }
    int excl = s[tid] - sum;
    g_start[4 * tid + 0] = excl;
    g_start[4 * tid + 1] = excl + t1;
    g_start[4 * tid + 2] = excl + t2;
    g_start[4 * tid + 3] = excl + t3;
    if (tid == 1023) g_start[NCELLS] = s[1023];
}

// ---------------------------------------------------------------------------
// Kernel 3: scatter particle ids into cell-grouped order. atomicSub drains
// g_cnt back to zero (self-cleaning for the next replay).
// ---------------------------------------------------------------------------
__global__ __launch_bounds__(256)
void scatter_kernel() {
    const int i = blockIdx.x * 256 + threadIdx.x;
    int c = g_cellid[i];
    int r = atomicSub(&g_cnt[c], 1) - 1;
    g_sortedidx[g_start[c] + r] = i;
}

// ---------------------------------------------------------------------------
// Heavy path (ordered form, j-side mask only, matching the reference's
// column-masked eps_mat). j-side data loaded from global (L2-hot).
// ---------------------------------------------------------------------------
__device__ __forceinline__ float pair_e(float r2, float ri, float rj, float mj,
                                        const float* __restrict__ wi,
                                        const float* __restrict__ ci,
                                        int j, const float* __restrict__ ct) {
    float dr = sqrtf(r2);
    float t  = R_C2 - r2;
    float poly = t * t * (R_C2 + 2.0f * r2 - 3.0f * R_ON2) * CUT_INV_DENOM;
    float cut  = (r2 < R_ON2) ? 1.0f : poly;
    const float4* __restrict__ cj4 = (const float4*)(ct + j * NC);
    const float4* __restrict__ wj4 = (const float4*)(g_w + j * NC);
    float dot = 0.0f;
#pragma unroll
    for (int q = 0; q < 4; q++) {
        float4 cj = cj4[q];
        float4 wj = wj4[q];
        dot = fmaf(wi[q * 4 + 0], cj.x, dot); dot = fmaf(wj.x, ci[q * 4 + 0], dot);
        dot = fmaf(wi[q * 4 + 1], cj.y, dot); dot = fmaf(wj.y, ci[q * 4 + 1], dot);
        dot = fmaf(wi[q * 4 + 2], cj.z, dot); dot = fmaf(wj.z, ci[q * 4 + 2], dot);
        dot = fmaf(wi[q * 4 + 3], cj.w, dot); dot = fmaf(wj.w, ci[q * 4 + 3], dot);
    }
    float er  = 0.5f * dot;
    float eps = (__fdividef(5.0f, 1.0f + __expf(-er)) + 0.3f) * mj;
    float u   = 1.0f - __expf(-ALPHA_F * (dr - (ri + rj)));
    return eps * (u * u - 1.0f) * cut;
}

// ---------------------------------------------------------------------------
// Kernel 4: energy via cell list. One warp per particle; lane l < 27 owns one
// neighbor cell and processes its members in ascending particle-index order
// (min-selection; cells hold ~1 member) for determinism. Fixed-order shfl +
// smem tree reductions; fused last-block final reduction.
// ---------------------------------------------------------------------------
__global__ __launch_bounds__(256)
void energy_kernel(const float* __restrict__ ct, float* __restrict__ out) {
    __shared__ float warpsum[8];
    __shared__ float red[256];
    __shared__ bool  is_last;

    const int tid  = threadIdx.x;
    const int lane = tid & 31;
    const int wrp  = tid >> 5;
    const int i    = blockIdx.x * 8 + wrp;

    const float4 pi = g_pos4[i];
    const int cid = g_cellid[i];

    float acc = 0.0f;

    if (lane < 27) {
        int cx = (cid & 15) + lane % 3 - 1;
        int cy = ((cid >> 4) & 15) + (lane / 3) % 3 - 1;
        int cz = (cid >> 8) + lane / 9 - 1;
        if (cx >= 0 && cx < NCELL_DIM && cy >= 0 && cy < NCELL_DIM &&
            cz >= 0 && cz < NCELL_DIM) {
            int nc = (cz << 8) | (cy << 4) | cx;
            int s = g_start[nc];
            int e = g_start[nc + 1];
            if (e > s) {
                // i-side data in registers (same for all lanes; L1 broadcast)
                const float4* __restrict__ wi4 = (const float4*)(g_w + i * NC);
                const float4* __restrict__ ci4 = (const float4*)(ct + i * NC);
                float wi[16], ci[16];
#pragma unroll
                for (int q = 0; q < 4; q++) {
                    float4 wv = wi4[q], cv = ci4[q];
                    wi[q * 4 + 0] = wv.x; wi[q * 4 + 1] = wv.y;
                    wi[q * 4 + 2] = wv.z; wi[q * 4 + 3] = wv.w;
                    ci[q * 4 + 0] = cv.x; ci[q * 4 + 1] = cv.y;
                    ci[q * 4 + 2] = cv.z; ci[q * 4 + 3] = cv.w;
                }
                // process members in ascending particle-index order
                int last = -1;
                for (int m = s; m < e; m++) {
                    int best = 1 << 30;
                    for (int u = s; u < e; u++) {
                        int j = g_sortedidx[u];
                        if (j > last && j < best) best = j;
                    }
                    last = best;
                    if (best == i) continue;
                    float4 pj = g_pos4[best];
                    float dx = pi.x - pj.x, dy = pi.y - pj.y, dz = pi.z - pj.z;
                    float r2 = fmaf(dx, dx, fmaf(dy, dy, dz * dz));
                    if (r2 < R_C2) {
                        acc += pair_e(r2, pi.w, pj.w, g_mask[best], wi, ci, best, ct);
                    }
                }
            }
        }
    }

    // fixed-order warp reduction
#pragma unroll
    for (int off = 16; off > 0; off >>= 1) {
        acc += __shfl_down_sync(0xffffffffu, acc, off);
    }
    if (lane == 0) warpsum[wrp] = acc;
    __syncthreads();

    // fixed-order block reduction of 8 warp sums
    if (tid == 0) {
        float b = 0.0f;
#pragma unroll
        for (int k = 0; k < 8; k++) b += warpsum[k];
        g_part[blockIdx.x] = b;
        __threadfence();
        unsigned int done = atomicAdd(&g_count, 1u);
        is_last = (done == EBLOCKS - 1);
    }
    __syncthreads();

    // last block: deterministic final reduction + counter reset
    if (is_last) {
        red[tid] = g_part[tid] + g_part[tid + 256];
        __syncthreads();
#pragma unroll
        for (int sfr = 128; sfr > 0; sfr >>= 1) {
            if (tid < sfr) red[tid] += red[tid + sfr];
            __syncthreads();
        }
        if (tid == 0) {
            out[0] = 0.5f * red[0];
            g_count = 0;   // restore invariant for next replay
        }
    }
}

// ---------------------------------------------------------------------------
// Launch. Inputs (metadata order): position (N*3), celltype (N*16),
// epsilon (N*256), radius (N). Output: scalar float.
// ---------------------------------------------------------------------------
extern "C" void kernel_launch(void* const* d_in, const int* in_sizes, int n_in,
                              void* d_out, int out_size) {
    const float* pos = (const float*)d_in[0];
    const float* ct  = (const float*)d_in[1];
    const float* E   = (const float*)d_in[2];
    const float* rad = (const float*)d_in[3];
    float* out = (float*)d_out;

    prep_kernel<<<NPART * NC / 128, 128>>>(pos, ct, E, rad);
    scan_kernel<<<1, 1024>>>();
    scatter_kernel<<<NPART / 256, 256>>>();
    energy_kernel<<<EBLOCKS, 256>>>(ct, out);
}